// round 1
// baseline (speedup 1.0000x reference)
#include <cuda_runtime.h>
#include <cstdint>
#include <cstddef>

#define BB 8
#define NN 16384
#define MM 256
#define CC 128
#define NS 32
#define FPS_T 512
#define NPAIR 16  /* 32 points per thread, packed as 16 f32x2 pairs */

/* output layout (concatenated, float32) */
#define GP_OFF 0                      /* grouped_p [8,3,256,32]  */
#define CP_OFF 196608                 /* center_p  [8,256,3]     */
#define FJ_OFF 202752                 /* fj        [8,128,256,32]*/
#define CX_OFF 8591360                /* center_x  [8,128,256,1] */

__device__ int g_fpsidx[BB * MM];
__device__ int g_nidx[BB * MM * NS];

/* ---------- exact-rounding f32x2 helpers (no FMA contraction) ---------- */
__device__ __forceinline__ unsigned long long pk2(float lo, float hi) {
    unsigned long long r;
    asm("mov.b64 %0, {%1,%2};" : "=l"(r) : "f"(lo), "f"(hi));
    return r;
}
__device__ __forceinline__ float2 upk2(unsigned long long v) {
    float2 r;
    asm("mov.b64 {%0,%1}, %2;" : "=f"(r.x), "=f"(r.y) : "l"(v));
    return r;
}
__device__ __forceinline__ unsigned long long add2(unsigned long long a, unsigned long long b) {
    unsigned long long r;
    asm("add.rn.f32x2 %0, %1, %2;" : "=l"(r) : "l"(a), "l"(b));
    return r;
}
__device__ __forceinline__ unsigned long long mul2(unsigned long long a, unsigned long long b) {
    unsigned long long r;
    asm("mul.rn.f32x2 %0, %1, %2;" : "=l"(r) : "l"(a), "l"(b));
    return r;
}

/* =======================================================================
 * Kernel 1: FPS. One CTA per batch, 512 threads, 32 points/thread.
 * Coords in registers (f32x2 pairs), dist in 64KB dynamic SMEM (float2,
 * layout dist2[q*512+t] holds points (2q)*512+t and (2q+1)*512+t).
 * Lazy per-thread argmax: rescan only when own best's dist decreased.
 * Replicates reference rounding exactly: d=((dx^2+dy^2)+dz^2), min, argmax
 * with first-index ties.
 * ===================================================================== */
__global__ void __launch_bounds__(FPS_T, 1)
fps_kernel(const float* __restrict__ p, float* __restrict__ out)
{
    extern __shared__ float2 dist2[];          /* NN/2 float2 = 64KB      */
    __shared__ float redv[16];
    __shared__ int   redi[16];
    __shared__ int   s_widx;
    __shared__ float s_c[3];

    const int t = threadIdx.x;
    const int b = blockIdx.x;
    const float* __restrict__ pb = p + (size_t)b * NN * 3;
    float* __restrict__ centerP = out + CP_OFF;

    unsigned long long X[NPAIR], Y[NPAIR], Z[NPAIR];
#pragma unroll
    for (int q = 0; q < NPAIR; q++) {
        int n0 = (2 * q) * FPS_T + t;
        int n1 = n0 + FPS_T;
        float x0 = pb[n0 * 3 + 0], y0 = pb[n0 * 3 + 1], z0 = pb[n0 * 3 + 2];
        float x1 = pb[n1 * 3 + 0], y1 = pb[n1 * 3 + 1], z1 = pb[n1 * 3 + 2];
        X[q] = pk2(x0, x1); Y[q] = pk2(y0, y1); Z[q] = pk2(z0, z1);
    }
    for (int i = t; i < NN / 2; i += FPS_T)
        dist2[i] = make_float2(1e10f, 1e10f);

    if (t == 0) {  /* center 0 is point 0 (owned by thread 0, pair 0, lo) */
        float2 fx = upk2(X[0]), fy = upk2(Y[0]), fz = upk2(Z[0]);
        s_c[0] = fx.x; s_c[1] = fy.x; s_c[2] = fz.x;
        g_fpsidx[b * MM + 0] = 0;
        centerP[(b * MM + 0) * 3 + 0] = fx.x;
        centerP[(b * MM + 0) * 3 + 1] = fy.x;
        centerP[(b * MM + 0) * 3 + 2] = fz.x;
    }
    __syncthreads();

    float best = -1.0f;
    int   bidx = 0;

    for (int m = 1; m < MM; m++) {
        const float cx = s_c[0], cy = s_c[1], cz = s_c[2];
        const unsigned long long ncx = pk2(-cx, -cx);
        const unsigned long long ncy = pk2(-cy, -cy);
        const unsigned long long ncz = pk2(-cz, -cz);

#pragma unroll
        for (int q = 0; q < NPAIR; q++) {
            unsigned long long dx = add2(X[q], ncx);
            unsigned long long dy = add2(Y[q], ncy);
            unsigned long long dz = add2(Z[q], ncz);
            unsigned long long dd = add2(add2(mul2(dx, dx), mul2(dy, dy)), mul2(dz, dz));
            float2 dv = upk2(dd);
            float2 o  = dist2[q * FPS_T + t];
            if (dv.x < o.x) dist2[q * FPS_T + t].x = dv.x;
            if (dv.y < o.y) dist2[q * FPS_T + t].y = dv.y;
        }

        /* lazy argmax maintenance: only rescan when our best decreased */
        bool need = (m == 1);
        if (!need) {
            int qb = bidx >> 10, e = (bidx >> 9) & 1;
            float2 pv = dist2[qb * FPS_T + t];
            float v = e ? pv.y : pv.x;
            need = (v < best);
        }
        if (need) {
            best = -1.0f; bidx = t;
            for (int q = 0; q < NPAIR; q++) {
                float2 v = dist2[q * FPS_T + t];
                int n0 = (2 * q) * FPS_T + t;
                if (v.x > best) { best = v.x; bidx = n0; }
                if (v.y > best) { best = v.y; bidx = n0 + FPS_T; }
            }
        }

        /* block argmax (value desc, index asc on ties = first-max) */
        float rv = best; int ri = bidx;
#pragma unroll
        for (int off = 16; off > 0; off >>= 1) {
            float ov = __shfl_down_sync(0xffffffffu, rv, off);
            int   oi = __shfl_down_sync(0xffffffffu, ri, off);
            if (ov > rv || (ov == rv && oi < ri)) { rv = ov; ri = oi; }
        }
        if ((t & 31) == 0) { redv[t >> 5] = rv; redi[t >> 5] = ri; }
        __syncthreads();
        if (t < 32) {
            float v2 = (t < 16) ? redv[t] : -2.0f;
            int   i2 = (t < 16) ? redi[t] : 0x7fffffff;
#pragma unroll
            for (int off = 16; off > 0; off >>= 1) {
                float ov = __shfl_down_sync(0xffffffffu, v2, off);
                int   oi = __shfl_down_sync(0xffffffffu, i2, off);
                if (ov > v2 || (ov == v2 && oi < i2)) { v2 = ov; i2 = oi; }
            }
            if (t == 0) s_widx = i2;
        }
        __syncthreads();

        const int widx = s_widx;
        if ((widx & (FPS_T - 1)) == t) {     /* owner publishes coords */
            int qo = widx >> 10, e = (widx >> 9) & 1;
            float ox = 0.f, oy = 0.f, oz = 0.f;
#pragma unroll
            for (int q = 0; q < NPAIR; q++) {
                if (q == qo) {
                    float2 fx = upk2(X[q]), fy = upk2(Y[q]), fz = upk2(Z[q]);
                    ox = e ? fx.y : fx.x;
                    oy = e ? fy.y : fy.x;
                    oz = e ? fz.y : fz.x;
                }
            }
            s_c[0] = ox; s_c[1] = oy; s_c[2] = oz;
            g_fpsidx[b * MM + m] = widx;
            centerP[(b * MM + m) * 3 + 0] = ox;
            centerP[(b * MM + m) * 3 + 1] = oy;
            centerP[(b * MM + m) * 3 + 2] = oz;
        }
        __syncthreads();
    }
}

/* =======================================================================
 * Kernel 2: ball query. One warp per (b,m) center; ordered scan of 32-wide
 * chunks, ballot + prefix-popc append of first 32 in-radius indices, early
 * exit, pad with first neighbor. Also writes grouped_p (= p[nidx]-center).
 * ===================================================================== */
__global__ void __launch_bounds__(256)
ballquery_kernel(const float* __restrict__ p, float* __restrict__ out)
{
    __shared__ int sidx[8][NS];
    const int lane = threadIdx.x & 31;
    const int wloc = threadIdx.x >> 5;
    const int gw   = blockIdx.x * 8 + wloc;      /* 0..2047 */
    const int b = gw >> 8;
    const int m = gw & (MM - 1);

    const float* __restrict__ centerP = out + CP_OFF;
    const float cx = centerP[(b * MM + m) * 3 + 0];
    const float cy = centerP[(b * MM + m) * 3 + 1];
    const float cz = centerP[(b * MM + m) * 3 + 2];
    const float R2 = 0.01f;  /* == f32(double 0.1*0.1), matches reference */

    const float* __restrict__ pb = p + (size_t)b * NN * 3;

    int cnt = 0;
    for (int base = 0; base < NN; base += 32) {
        if (cnt >= NS) break;
        const int n = base + lane;
        const float sx = pb[n * 3 + 0];
        const float sy = pb[n * 3 + 1];
        const float sz = pb[n * 3 + 2];
        const float dx = __fsub_rn(cx, sx);
        const float dy = __fsub_rn(cy, sy);
        const float dz = __fsub_rn(cz, sz);
        const float d2 = __fadd_rn(__fadd_rn(__fmul_rn(dx, dx), __fmul_rn(dy, dy)),
                                   __fmul_rn(dz, dz));
        const bool w = d2 < R2;
        const unsigned mask = __ballot_sync(0xffffffffu, w);
        const int pos = cnt + __popc(mask & ((1u << lane) - 1u));
        if (w && pos < NS) sidx[wloc][pos] = n;
        cnt += __popc(mask);
    }
    if (cnt > NS) cnt = NS;
    __syncwarp();

    const int first = sidx[wloc][0];           /* >=1 always: center itself */
    const int myidx = (lane < cnt) ? sidx[wloc][lane] : first;
    g_nidx[(b * MM + m) * NS + lane] = myidx;

    const float gx = pb[myidx * 3 + 0];
    const float gy = pb[myidx * 3 + 1];
    const float gz = pb[myidx * 3 + 2];
    float* __restrict__ gp = out + GP_OFF;
    gp[((size_t)(b * 3 + 0) * MM + m) * NS + lane] = __fsub_rn(gx, cx);
    gp[((size_t)(b * 3 + 1) * MM + m) * NS + lane] = __fsub_rn(gy, cy);
    gp[((size_t)(b * 3 + 2) * MM + m) * NS + lane] = __fsub_rn(gz, cz);
}

/* =======================================================================
 * Kernel 3: feature gathers. Block per (b,m); 256 threads = 8 channels x
 * 32 samples per step, 16 steps over C=128. Coalesced fj writes; x reads
 * gathered but L2-friendly. Also writes center_x.
 * ===================================================================== */
__global__ void __launch_bounds__(256)
gather_kernel(const float* __restrict__ x, float* __restrict__ out)
{
    __shared__ int sidx[NS];
    __shared__ int scidx;
    const int bm = blockIdx.x;                 /* b*256+m */
    const int b  = bm >> 8;
    const int m  = bm & (MM - 1);
    const int tid = threadIdx.x;

    if (tid < NS) sidx[tid] = g_nidx[bm * NS + tid];
    if (tid == 0) scidx = g_fpsidx[bm];
    __syncthreads();

    const int s  = tid & 31;
    const int cl = tid >> 5;                   /* 0..7 */
    const float* __restrict__ xb = x + (size_t)b * CC * NN;
    float* __restrict__ fj = out + FJ_OFF;
    float* __restrict__ cxo = out + CX_OFF;
    const int ci = scidx;
    const int myn = sidx[s];

#pragma unroll
    for (int r = 0; r < 16; r++) {
        const int c = r * 8 + cl;
        const float* __restrict__ row = xb + (size_t)c * NN;
        fj[(((size_t)(b * CC + c) * MM + m) << 5) + s] = __ldg(row + myn);
        if (s == 0)
            cxo[(size_t)(b * CC + c) * MM + m] = __ldg(row + ci);
    }
}

/* ======================================================================= */
extern "C" void kernel_launch(void* const* d_in, const int* in_sizes, int n_in,
                              void* d_out, int out_size)
{
    const float* p = (const float*)d_in[0];
    const float* x = (const float*)d_in[1];
    if (n_in >= 2 && in_sizes[0] > in_sizes[1]) {  /* defensive: p is smaller */
        p = (const float*)d_in[1];
        x = (const float*)d_in[0];
    }
    float* out = (float*)d_out;

    cudaFuncSetAttribute(fps_kernel, cudaFuncAttributeMaxDynamicSharedMemorySize, 65536);

    fps_kernel<<<BB, FPS_T, 65536>>>(p, out);
    ballquery_kernel<<<(BB * MM) / 8, 256>>>(p, out);
    gather_kernel<<<BB * MM, 256>>>(x, out);
}

// round 2
// speedup vs baseline: 1.5735x; 1.5735x over previous
#include <cuda_runtime.h>
#include <cstdint>
#include <cstddef>

#define BB 8
#define NN 16384
#define MM 256
#define CC 128
#define NS 32
#define FPS_T 512
#define CLU 8                 /* cluster size: CTAs per batch       */
#define PPT 4                 /* points per thread in FPS           */

/* output layout (concatenated, float32) */
#define GP_OFF 0                      /* grouped_p [8,3,256,32]  */
#define CP_OFF 196608                 /* center_p  [8,256,3]     */
#define FJ_OFF 202752                 /* fj        [8,128,256,32]*/
#define CX_OFF 8591360                /* center_x  [8,128,256,1] */

__device__ int g_fpsidx[BB * MM];
__device__ int g_nidx[BB * MM * NS];

/* ---------- exact-rounding f32x2 helpers (no FMA contraction) ---------- */
__device__ __forceinline__ unsigned long long pk2(float lo, float hi) {
    unsigned long long r;
    asm("mov.b64 %0, {%1,%2};" : "=l"(r) : "f"(lo), "f"(hi));
    return r;
}
__device__ __forceinline__ float2 upk2(unsigned long long v) {
    float2 r;
    asm("mov.b64 {%0,%1}, %2;" : "=f"(r.x), "=f"(r.y) : "l"(v));
    return r;
}
__device__ __forceinline__ unsigned long long add2(unsigned long long a, unsigned long long b) {
    unsigned long long r;
    asm("add.rn.f32x2 %0, %1, %2;" : "=l"(r) : "l"(a), "l"(b));
    return r;
}
__device__ __forceinline__ unsigned long long mul2(unsigned long long a, unsigned long long b) {
    unsigned long long r;
    asm("mul.rn.f32x2 %0, %1, %2;" : "=l"(r) : "l"(a), "l"(b));
    return r;
}
__device__ __forceinline__ uint32_t smem_u32(const void* p) {
    uint32_t a;
    asm("{ .reg .u64 t; cvta.to.shared.u64 t, %1; cvt.u32.u64 %0, t; }"
        : "=r"(a) : "l"(p));
    return a;
}
__device__ __forceinline__ uint32_t mapa_u32(uint32_t local, uint32_t rank) {
    uint32_t r;
    asm("mapa.shared::cluster.u32 %0, %1, %2;" : "=r"(r) : "r"(local), "r"(rank));
    return r;
}
__device__ __forceinline__ void st_clu64(uint32_t addr, unsigned long long v) {
    asm volatile("st.shared::cluster.u64 [%0], %1;" :: "r"(addr), "l"(v) : "memory");
}
__device__ __forceinline__ unsigned long long pkfi(float f, int i) {
    unsigned long long r;
    asm("mov.b64 %0, {%1,%2};" : "=l"(r) : "f"(f), "r"(i));
    return r;
}

/* candidate compare: larger v wins; equal v -> lower index wins (first-max) */
#define CAND_TAKE(ov, oi, v, i) ((ov) > (v) || ((ov) == (v) && (oi) < (i)))

/* =======================================================================
 * Kernel 1: FPS, cluster-distributed. 8 CTAs/batch x 512 thr; each thread
 * owns 4 points (2 f32x2 pairs, coords + dists in registers). Per iter:
 * packed exact update -> warp shfl reduce (v,i,x,y,z) -> block reduce in
 * warp0 -> DSMEM push of CTA candidate to all ranks (double-buffered) ->
 * one cluster.sync -> every thread reduces 8 slots locally.
 * ===================================================================== */
__global__ void __launch_bounds__(FPS_T, 1) __cluster_dims__(CLU, 1, 1)
fps_kernel(const float* __restrict__ p, float* __restrict__ out)
{
    __shared__ float cv[16]; __shared__ int ci[16];
    __shared__ float cxs[16], cys[16], czs[16];
    __shared__ unsigned long long slots[2][CLU][3];  /* {v,i}{x,y}{z,-} */

    const int t = threadIdx.x;
    const int r = blockIdx.x & (CLU - 1);
    const int b = blockIdx.x / CLU;
    const int w = t >> 5, lane = t & 31;
    const int nbase = r * (NN / CLU) + t;            /* +k*512, k=0..3 */
    const float* __restrict__ pb = p + (size_t)b * NN * 3;
    float* __restrict__ centerP = out + CP_OFF;

    /* coords: pairs (k0,k1)=(0,1), (k2,k3)=(2,3) */
    unsigned long long X[2], Y[2], Z[2];
#pragma unroll
    for (int q = 0; q < 2; q++) {
        int n0 = nbase + (2 * q) * FPS_T;
        int n1 = n0 + FPS_T;
        X[q] = pk2(pb[n0 * 3 + 0], pb[n1 * 3 + 0]);
        Y[q] = pk2(pb[n0 * 3 + 1], pb[n1 * 3 + 1]);
        Z[q] = pk2(pb[n0 * 3 + 2], pb[n1 * 3 + 2]);
    }
    float d0 = 1e10f, d1 = 1e10f, d2 = 1e10f, d3 = 1e10f;

    /* center 0 = global point 0 */
    float cx = pb[0], cy = pb[1], cz = pb[2];
    if (r == 0 && t == 0) {
        g_fpsidx[b * MM + 0] = 0;
        centerP[(b * MM + 0) * 3 + 0] = cx;
        centerP[(b * MM + 0) * 3 + 1] = cy;
        centerP[(b * MM + 0) * 3 + 2] = cz;
    }

    for (int m = 1; m < MM; m++) {
        const unsigned long long ncx = pk2(-cx, -cx);
        const unsigned long long ncy = pk2(-cy, -cy);
        const unsigned long long ncz = pk2(-cz, -cz);

        /* exact packed distance update: ((dx*dx+dy*dy)+dz*dz), then min */
        {
            unsigned long long dx = add2(X[0], ncx);
            unsigned long long dy = add2(Y[0], ncy);
            unsigned long long dz = add2(Z[0], ncz);
            float2 dv = upk2(add2(add2(mul2(dx, dx), mul2(dy, dy)), mul2(dz, dz)));
            d0 = fminf(d0, dv.x); d1 = fminf(d1, dv.y);
        }
        {
            unsigned long long dx = add2(X[1], ncx);
            unsigned long long dy = add2(Y[1], ncy);
            unsigned long long dz = add2(Z[1], ncz);
            float2 dv = upk2(add2(add2(mul2(dx, dx), mul2(dy, dy)), mul2(dz, dz)));
            d2 = fminf(d2, dv.x); d3 = fminf(d3, dv.y);
        }

        /* thread-local argmax over 4 points (ascending k keeps first-max) */
        float bv = d0; int bk = 0;
        if (d1 > bv) { bv = d1; bk = 1; }
        if (d2 > bv) { bv = d2; bk = 2; }
        if (d3 > bv) { bv = d3; bk = 3; }
        int bi = nbase + bk * FPS_T;
        float2 f0 = upk2(X[0]), f1 = upk2(X[1]);
        float bx = (bk == 0) ? f0.x : (bk == 1) ? f0.y : (bk == 2) ? f1.x : f1.y;
        f0 = upk2(Y[0]); f1 = upk2(Y[1]);
        float by = (bk == 0) ? f0.x : (bk == 1) ? f0.y : (bk == 2) ? f1.x : f1.y;
        f0 = upk2(Z[0]); f1 = upk2(Z[1]);
        float bz = (bk == 0) ? f0.x : (bk == 1) ? f0.y : (bk == 2) ? f1.x : f1.y;

        /* warp reduce with coords payload */
#pragma unroll
        for (int off = 16; off > 0; off >>= 1) {
            float ov = __shfl_down_sync(0xffffffffu, bv, off);
            int   oi = __shfl_down_sync(0xffffffffu, bi, off);
            float ox = __shfl_down_sync(0xffffffffu, bx, off);
            float oy = __shfl_down_sync(0xffffffffu, by, off);
            float oz = __shfl_down_sync(0xffffffffu, bz, off);
            if (CAND_TAKE(ov, oi, bv, bi)) { bv = ov; bi = oi; bx = ox; by = oy; bz = oz; }
        }
        if (lane == 0) { cv[w] = bv; ci[w] = bi; cxs[w] = bx; cys[w] = by; czs[w] = bz; }
        __syncthreads();

        /* warp0: reduce 16 CTA-local candidates, push to all ranks */
        if (w == 0) {
            float v2 = (lane < 16) ? cv[lane] : -1.0f;
            int   i2 = (lane < 16) ? ci[lane] : 0x7fffffff;
            float x2 = (lane < 16) ? cxs[lane] : 0.f;
            float y2 = (lane < 16) ? cys[lane] : 0.f;
            float z2 = (lane < 16) ? czs[lane] : 0.f;
#pragma unroll
            for (int off = 16; off > 0; off >>= 1) {
                float ov = __shfl_down_sync(0xffffffffu, v2, off);
                int   oi = __shfl_down_sync(0xffffffffu, i2, off);
                float ox = __shfl_down_sync(0xffffffffu, x2, off);
                float oy = __shfl_down_sync(0xffffffffu, y2, off);
                float oz = __shfl_down_sync(0xffffffffu, z2, off);
                if (CAND_TAKE(ov, oi, v2, i2)) { v2 = ov; i2 = oi; x2 = ox; y2 = oy; z2 = oz; }
            }
            /* broadcast winner to lanes 0..7, each pushes to rank=lane */
            v2 = __shfl_sync(0xffffffffu, v2, 0);
            i2 = __shfl_sync(0xffffffffu, i2, 0);
            x2 = __shfl_sync(0xffffffffu, x2, 0);
            y2 = __shfl_sync(0xffffffffu, y2, 0);
            z2 = __shfl_sync(0xffffffffu, z2, 0);
            if (lane < CLU) {
                uint32_t laddr = smem_u32(&slots[m & 1][r][0]);
                uint32_t raddr = mapa_u32(laddr, (uint32_t)lane);
                st_clu64(raddr,      pkfi(v2, i2));
                st_clu64(raddr + 8,  pk2(x2, y2));
                st_clu64(raddr + 16, pk2(z2, 0.f));
            }
        }

        asm volatile("barrier.cluster.arrive.aligned;" ::: "memory");
        asm volatile("barrier.cluster.wait.aligned;" ::: "memory");

        /* every thread reduces the 8 rank-ordered slots */
        float wv = -1.0f, wx = 0.f, wy = 0.f, wz = 0.f; int wi = 0x7fffffff;
#pragma unroll
        for (int k = 0; k < CLU; k++) {
            float2 vi = upk2(slots[m & 1][k][0]);
            float sv = vi.x; int si = __float_as_int(vi.y);
            if (CAND_TAKE(sv, si, wv, wi)) {
                wv = sv; wi = si;
                float2 xy = upk2(slots[m & 1][k][1]);
                float2 zp = upk2(slots[m & 1][k][2]);
                wx = xy.x; wy = xy.y; wz = zp.x;
            }
        }
        cx = wx; cy = wy; cz = wz;
        if (r == 0 && t == 0) {
            g_fpsidx[b * MM + m] = wi;
            centerP[(b * MM + m) * 3 + 0] = wx;
            centerP[(b * MM + m) * 3 + 1] = wy;
            centerP[(b * MM + m) * 3 + 2] = wz;
        }
    }
}

/* =======================================================================
 * Kernel 2: ball query, warp per center. 4 chunks (128 pts) per exit
 * check for MLP; ballot + prefix-popc ordered append; pad with first.
 * Also writes grouped_p (= p[nidx]-center), exact __fsub_rn.
 * ===================================================================== */
__global__ void __launch_bounds__(256)
ballquery_kernel(const float* __restrict__ p, float* __restrict__ out)
{
    __shared__ int sidx[8][NS];
    const int lane = threadIdx.x & 31;
    const int wloc = threadIdx.x >> 5;
    const int gw   = blockIdx.x * 8 + wloc;
    const int b = gw >> 8;
    const int m = gw & (MM - 1);

    const float* __restrict__ centerP = out + CP_OFF;
    const float cx = centerP[(b * MM + m) * 3 + 0];
    const float cy = centerP[(b * MM + m) * 3 + 1];
    const float cz = centerP[(b * MM + m) * 3 + 2];
    const float R2 = 0.01f;

    const float* __restrict__ pb = p + (size_t)b * NN * 3;

    int cnt = 0;
    for (int base = 0; base < NN && cnt < NS; base += 128) {
        unsigned msk[4];
#pragma unroll
        for (int j = 0; j < 4; j++) {
            const int n = base + j * 32 + lane;
            const float dx = __fsub_rn(cx, pb[n * 3 + 0]);
            const float dy = __fsub_rn(cy, pb[n * 3 + 1]);
            const float dz = __fsub_rn(cz, pb[n * 3 + 2]);
            const float d2 = __fadd_rn(__fadd_rn(__fmul_rn(dx, dx), __fmul_rn(dy, dy)),
                                       __fmul_rn(dz, dz));
            msk[j] = __ballot_sync(0xffffffffu, d2 < R2);
        }
#pragma unroll
        for (int j = 0; j < 4; j++) {
            const int n = base + j * 32 + lane;
            const bool in = (msk[j] >> lane) & 1u;
            const int pos = cnt + __popc(msk[j] & ((1u << lane) - 1u));
            if (in && pos < NS) sidx[wloc][pos] = n;
            cnt += __popc(msk[j]);
        }
    }
    if (cnt > NS) cnt = NS;
    __syncwarp();

    const int first = sidx[wloc][0];
    const int myidx = (lane < cnt) ? sidx[wloc][lane] : first;
    g_nidx[(b * MM + m) * NS + lane] = myidx;

    const float gx = pb[myidx * 3 + 0];
    const float gy = pb[myidx * 3 + 1];
    const float gz = pb[myidx * 3 + 2];
    float* __restrict__ gp = out + GP_OFF;
    gp[((size_t)(b * 3 + 0) * MM + m) * NS + lane] = __fsub_rn(gx, cx);
    gp[((size_t)(b * 3 + 1) * MM + m) * NS + lane] = __fsub_rn(gy, cy);
    gp[((size_t)(b * 3 + 2) * MM + m) * NS + lane] = __fsub_rn(gz, cz);
}

/* =======================================================================
 * Kernel 3: feature gathers. Block per (b,m); 8 channels x 32 samples
 * per step, 16 steps over C=128. Coalesced fj writes.
 * ===================================================================== */
__global__ void __launch_bounds__(256)
gather_kernel(const float* __restrict__ x, float* __restrict__ out)
{
    __shared__ int sidx[NS];
    __shared__ int scidx;
    const int bm = blockIdx.x;
    const int b  = bm >> 8;
    const int m  = bm & (MM - 1);
    const int tid = threadIdx.x;

    if (tid < NS) sidx[tid] = g_nidx[bm * NS + tid];
    if (tid == 0) scidx = g_fpsidx[bm];
    __syncthreads();

    const int s  = tid & 31;
    const int cl = tid >> 5;
    const float* __restrict__ xb = x + (size_t)b * CC * NN;
    float* __restrict__ fj = out + FJ_OFF;
    float* __restrict__ cxo = out + CX_OFF;
    const int ci = scidx;
    const int myn = sidx[s];

#pragma unroll
    for (int rr = 0; rr < 16; rr++) {
        const int c = rr * 8 + cl;
        const float* __restrict__ row = xb + (size_t)c * NN;
        fj[(((size_t)(b * CC + c) * MM + m) << 5) + s] = __ldg(row + myn);
        if (s == 0)
            cxo[(size_t)(b * CC + c) * MM + m] = __ldg(row + ci);
    }
}

/* ======================================================================= */
extern "C" void kernel_launch(void* const* d_in, const int* in_sizes, int n_in,
                              void* d_out, int out_size)
{
    const float* p = (const float*)d_in[0];
    const float* x = (const float*)d_in[1];
    if (n_in >= 2 && in_sizes[0] > in_sizes[1]) {
        p = (const float*)d_in[1];
        x = (const float*)d_in[0];
    }
    float* out = (float*)d_out;

    fps_kernel<<<BB * CLU, FPS_T>>>(p, out);
    ballquery_kernel<<<(BB * MM) / 8, 256>>>(p, out);
    gather_kernel<<<BB * MM, 256>>>(x, out);
}